// round 13
// baseline (speedup 1.0000x reference)
#include <cuda_runtime.h>
#include <math.h>

#define NQ 2
#define NBLOCKS 740
#define TPB 256

// ---- 2-point Gauss-Legendre on [-1,1] mapped to hx=(x+1)/2, weights = 1 ----
__device__ constexpr float hx_of(int q) {
    return (q == 0) ? 0.21132486540518713f : 0.78867513459481287f;
}

__device__ double d_acc;           // zero-init; reset by last block each launch
__device__ unsigned int d_count;   // zero-init; reset by last block each launch

__device__ __forceinline__ float ex2f(float x) {
    float y;
    asm("ex2.approx.ftz.f32 %0, %1;" : "=f"(y) : "f"(x));
    return y;
}
__device__ __forceinline__ float rcpf(float x) {
    float y;
    asm("rcp.approx.ftz.f32 %0, %1;" : "=f"(y) : "f"(x));
    return y;
}

// erfinv(1-2p) = Phi^{-1}(1-p)/sqrt(2), valid p in (0.05, 0.95).
// Cubic in L = log2(4p(1-p)); fit on L in [-2.4, 0], abs err <= ~4e-5.
__device__ __forceinline__ float ninv_half(float p) {
    const float x = fmaf(-2.0f, p, 1.0f);      // 1-2p
    const float t = fmaf(-x, x, 1.0f);         // 4p(1-p) in [0.19, 1]
    const float L = __log2f(t);
    float P = fmaf(7.9373e-4f, L, 5.51608e-3f);
    P = fmaf(P, L, -0.160841f);
    P = fmaf(P, L, 0.886227f);
    return x * P;
}

// A&S 7.1.25 erfc 3-term with the 0.5 prefactor folded into coefficients;
// t precomputed, eneg = exp(-h^2/2). Returns Phi(h).
__device__ __forceinline__ float phi_poly(float h, float t, float eneg) {
    float poly = fmaf(0.3739278f, t, -0.0479399f);
    poly = fmaf(poly, t, 0.1740121f);
    const float half_erfc = poly * t * eneg;
    return (h >= 0.0f) ? (1.0f - half_erfc) : half_erfc;
}

__global__ __launch_bounds__(TPB, 5) void loss_kernel(
    const float* __restrict__ yhat, const float* __restrict__ yv,
    const float* __restrict__ g12, const float* __restrict__ g34,
    const float* __restrict__ g3412, const float* __restrict__ s1p,
    const float* __restrict__ s2p, int n, float* __restrict__ out) {
    __shared__ float s_sc[11];
    __shared__ float4 s_cw[NQ];      // (c0, lw, A=c0*hx, pad)
    __shared__ double sd[TPB];

    const int tid = threadIdx.x;
    const int half = n >> 1;
    const int gid = blockIdx.x * blockDim.x + tid;
    const int stride = gridDim.x * blockDim.x;

    const float2* p3p = (const float2*)yhat;
    const float2* m1p = (const float2*)(yhat + n);
    const float2* p4p = (const float2*)(yhat + 2 * n);
    const float2* m2p = (const float2*)(yhat + 3 * n);
    const float2* l3p = (const float2*)yv;
    const float2* r1p = (const float2*)(yv + n);
    const float2* l4p = (const float2*)(yv + 2 * n);
    const float2* r2p = (const float2*)(yv + 3 * n);

    // ---- prologue loads FIRST: overlap DRAM latency with setup + barriers ----
    float2 p3, p4, m1, m2, r1, r2;
    int i = gid;
    if (i < half) {
        p3 = __ldg(p3p + i); p4 = __ldg(p4p + i);
        m1 = __ldg(m1p + i); m2 = __ldg(m2p + i);
        r1 = __ldg(r1p + i); r2 = __ldg(r2p + i);
    }

    if (tid == 0) {
        const float a = g12[0], b = g12[1], c = g12[2], d = g12[3];
        const float inv_det = 1.0f / (a * d - b * c);
        const float i00 = d * inv_det, i01 = -b * inv_det;
        const float i10 = -c * inv_det, i11 = a * inv_det;
        const float t0 = g3412[0], t1 = g3412[1], t2 = g3412[2], t3 = g3412[3];
        const float M00 = t0 * i00 + t1 * i10, M01 = t0 * i01 + t1 * i11;
        const float M10 = t2 * i00 + t3 * i10, M11 = t2 * i01 + t3 * i11;
        const float gs00 = g34[0] - (M00 * t0 + M01 * t1);
        const float gs01 = g34[1] - (M00 * t2 + M01 * t3);
        const float gs11 = g34[3] - (M10 * t2 + M11 * t3);
        const float s1g = sqrtf(gs00), s2g = sqrtf(gs11);
        const float rho = gs01 / (s1g * s2g);
        const float is1 = 1.0f / s1p[0], is2 = 1.0f / s2p[0];
        const float iv1 = 1.0f / s1g, iv2 = 1.0f / s2g;
        s_sc[0] = M00 * is1 * iv1; s_sc[1] = M01 * is2 * iv1;
        s_sc[2] = M10 * is1 * iv2; s_sc[3] = M11 * is2 * iv2;
        s_sc[4] = i00 * is1 * is1; s_sc[5] = (i01 + i10) * is1 * is2;
        s_sc[6] = i11 * is2 * is2;
        s_sc[7] = 1.41421356237309505f * iv1;   // sqrt(2)/s1g
        s_sc[8] = 1.41421356237309505f * iv2;   // sqrt(2)/s2g
        s_sc[9] = (rho >= 0.0f) ? 1.0f : -1.0f;
        s_sc[10] = 2.0f * rho;
    }
    __syncthreads();
    if (tid < NQ) {
        const float rho = 0.5f * s_sc[10];
        const float hx = hx_of(tid);
        const float r = rho * hx;
        const float omr2 = 1.0f - r * r;
        float4 cw;
        cw.x = 1.4426950408889634f / (2.0f * omr2);                    // c0
        const float amp = fabsf(rho) * 0.5f / (6.283185307179586f * sqrtf(omr2));
        cw.y = __log2f(amp);                                           // lw
        cw.z = cw.x * hx;                                              // A
        cw.w = 0.0f;
        s_cw[tid] = cw;
    }
    __syncthreads();

    const float M00 = s_sc[0], M01 = s_sc[1], M10 = s_sc[2], M11 = s_sc[3];
    const float i00 = s_sc[4], i01s = s_sc[5], i11 = s_sc[6];
    const float rt2s1 = s_sc[7], rt2s2 = s_sc[8], sgn = s_sc[9], rho2 = s_sc[10];
    const float4 cw0 = s_cw[0];
    const float4 cw1 = s_cw[1];

    float qsum = 0.0f;        // sum of quad terms
    float lsum = 0.0f;        // sum of per-iteration logs (rare path spill)
    float prodAll = 1.0f;     // running product of Ci values

    while (i < half) {
        // in-body label loads (used only at the final Ci combine)
        const float2 l3 = __ldg(l3p + i);
        const float2 l4 = __ldg(l4p + i);

        // ---- preamble: consume loaded registers ----
        const float d1a = r1.x - m1.x, d2a = r2.x - m2.x;
        const float mu1a = fmaf(M00, d1a, M01 * d2a);   // mu1/s1g
        const float mu2a = fmaf(M10, d1a, M11 * d2a);   // mu2/s2g
        const float quada = fmaf(d1a, fmaf(i00, d1a, i01s * d2a), i11 * d2a * d2a);
        const float ha = fmaf(ninv_half(p3.x), rt2s1, -mu1a);
        const float ka = fmaf(ninv_half(p4.x), rt2s2, -mu2a);

        const float d1b = r1.y - m1.y, d2b = r2.y - m2.y;
        const float mu1b = fmaf(M00, d1b, M01 * d2b);
        const float mu2b = fmaf(M10, d1b, M11 * d2b);
        const float quadb = fmaf(d1b, fmaf(i00, d1b, i01s * d2b), i11 * d2b * d2b);
        const float hb = fmaf(ninv_half(p3.y), rt2s1, -mu1b);
        const float kb = fmaf(ninv_half(p4.y), rt2s2, -mu2b);

        // ---- prefetch next iteration into the now-dead load registers ----
        const int inext = i + stride;
        const int ipf = (inext < half) ? inext : i;
        p3 = __ldg(p3p + ipf); p4 = __ldg(p4p + ipf);
        m1 = __ldg(m1p + ipf); m2 = __ldg(m2p + ipf);
        r1 = __ldg(r1p + ipf); r2 = __ldg(r2p + ipf);

        // ---- main math overlaps the prefetch latency ----
        const float h2a = ha * ha, k2a = ka * ka;
        const float eha = ex2f(-0.72134752044448170f * h2a);
        const float eka = ex2f(-0.72134752044448170f * k2a);
        const float h2b = hb * hb, k2b = kb * kb;
        const float ehb = ex2f(-0.72134752044448170f * h2b);
        const float ekb = ex2f(-0.72134752044448170f * k2b);

        // paired phi t-computation: one rcp per element (t = 1/(1+0.47047*z))
        const float uha = fmaf(0.33271137123566316f, fabsf(ha), 1.0f);
        const float uka = fmaf(0.33271137123566316f, fabsf(ka), 1.0f);
        const float invta = rcpf(uha * uka);
        const float P3a = phi_poly(ha, uka * invta, eha);
        const float P4a = phi_poly(ka, uha * invta, eka);

        const float uhb = fmaf(0.33271137123566316f, fabsf(hb), 1.0f);
        const float ukb = fmaf(0.33271137123566316f, fabsf(kb), 1.0f);
        const float invtb = rcpf(uhb * ukb);
        const float P3b = phi_poly(hb, ukb * invtb, ehb);
        const float P4b = phi_poly(kb, uhb * invtb, ekb);

        const float mSa = -(h2a + k2a);
        const float HKa = rho2 * ha * ka;
        const float mSb = -(h2b + k2b);
        const float HKb = rho2 * hb * kb;

        // GL-2 quadrature: expo = HK*A_q + (c0_q*mS + lw_q)
        const float acca = ex2f(fmaf(HKa, cw0.z, fmaf(cw0.x, mSa, cw0.y)))
                         + ex2f(fmaf(HKa, cw1.z, fmaf(cw1.x, mSa, cw1.y)));
        const float accb = ex2f(fmaf(HKb, cw0.z, fmaf(cw0.x, mSb, cw0.y)))
                         + ex2f(fmaf(HKb, cw1.z, fmaf(cw1.x, mSb, cw1.y)));

        const float Ba = fmaf(P3a, P4a, sgn * acca);
        const float Bb = fmaf(P3b, P4b, sgn * accb);

        // Algebraic corner combine (labels are exactly 0.0 or 1.0):
        //   Ci = s3*s4*B + s3*l4*P3 + s4*l3*P4 + l3*l4,  s = 1-2*l
        const float s3a = fmaf(-2.0f, l3.x, 1.0f);
        const float s4a = fmaf(-2.0f, l4.x, 1.0f);
        const float Cia = fmaf(s3a * s4a, Ba,
                          fmaf(s3a * l4.x, P3a,
                          fmaf(s4a * l3.x, P4a, l3.x * l4.x)));
        const float s3b = fmaf(-2.0f, l3.y, 1.0f);
        const float s4b = fmaf(-2.0f, l4.y, 1.0f);
        const float Cib = fmaf(s3b * s4b, Bb,
                          fmaf(s3b * l4.y, P3b,
                          fmaf(s4b * l3.y, P4b, l3.y * l4.y)));

        // running product; single log after the loop
        prodAll *= fmaxf(Cia, 1e-30f) * fmaxf(Cib, 1e-30f);
        qsum += quada + quadb;

        i = inext;
    }
    lsum += __logf(prodAll);

    // odd-n tail: one scalar element handled by global thread 0
    if ((n & 1) && gid == 0) {
        const int j = n - 1;
        const float d1 = yv[n + j] - yhat[n + j];
        const float d2 = yv[3 * n + j] - yhat[3 * n + j];
        const float mu1 = fmaf(M00, d1, M01 * d2);
        const float mu2 = fmaf(M10, d1, M11 * d2);
        const float quad = fmaf(d1, fmaf(i00, d1, i01s * d2), i11 * d2 * d2);
        const float h = fmaf(ninv_half(yhat[j]), rt2s1, -mu1);
        const float k = fmaf(ninv_half(yhat[2 * n + j]), rt2s2, -mu2);
        const float h2 = h * h, k2 = k * k;
        const float eh = ex2f(-0.72134752044448170f * h2);
        const float ek = ex2f(-0.72134752044448170f * k2);
        const float uh = fmaf(0.33271137123566316f, fabsf(h), 1.0f);
        const float uk = fmaf(0.33271137123566316f, fabsf(k), 1.0f);
        const float invt = rcpf(uh * uk);
        const float P3 = phi_poly(h, uk * invt, eh);
        const float P4 = phi_poly(k, uh * invt, ek);
        const float mS = -(h2 + k2);
        const float HK = rho2 * h * k;
        const float acc = ex2f(fmaf(HK, cw0.z, fmaf(cw0.x, mS, cw0.y)))
                        + ex2f(fmaf(HK, cw1.z, fmaf(cw1.x, mS, cw1.y)));
        const float B = fmaf(P3, P4, sgn * acc);
        const float l3s = yv[j], l4s = yv[2 * n + j];
        const float s3 = fmaf(-2.0f, l3s, 1.0f);
        const float s4 = fmaf(-2.0f, l4s, 1.0f);
        const float Ci = fmaf(s3 * s4, B,
                         fmaf(s3 * l4s, P3,
                         fmaf(s4 * l3s, P4, l3s * l4s)));
        qsum += quad;
        lsum += __logf(fmaxf(Ci, 1e-30f));
    }

    const float tsum = fmaf(-0.5f, qsum, lsum);

    // ---- deterministic in-block reduction ----
    sd[tid] = (double)tsum;
    __syncthreads();
#pragma unroll
    for (int s = TPB / 2; s > 0; s >>= 1) {
        if (tid < s) sd[tid] += sd[tid + s];
        __syncthreads();
    }

    // ---- grid reduction: one double atomicAdd per block; ticket-elected
    //      last block publishes the result and resets state for graph replay.
    if (tid == 0) {
        atomicAdd(&d_acc, sd[0]);
        __threadfence();
        const unsigned int old = atomicAdd(&d_count, 1u);
        if (old == gridDim.x - 1) {
            __threadfence();
            const double total = atomicAdd(&d_acc, 0.0);
            out[0] = (float)(-total);
            d_acc = 0.0;
            d_count = 0;
        }
    }
}

extern "C" void kernel_launch(void* const* d_in, const int* in_sizes, int n_in,
                              void* d_out, int out_size) {
    const float* yhat = (const float*)d_in[0];
    const float* yv = (const float*)d_in[1];
    const float* g12 = (const float*)d_in[2];
    const float* g34 = (const float*)d_in[3];
    const float* g3412 = (const float*)d_in[4];
    const float* s1 = (const float*)d_in[5];
    const float* s2 = (const float*)d_in[6];
    const int n = in_sizes[0] / 4;

    loss_kernel<<<NBLOCKS, TPB>>>(yhat, yv, g12, g34, g3412, s1, s2, n, (float*)d_out);
}

// round 14
// speedup vs baseline: 1.1481x; 1.1481x over previous
#include <cuda_runtime.h>
#include <math.h>

#define NQ 2
#define NBLOCKS 740
#define TPB 256

// ---- 2-point Gauss-Legendre on [-1,1] mapped to hx=(x+1)/2, weights = 1 ----
__device__ constexpr float hx_of(int q) {
    return (q == 0) ? 0.21132486540518713f : 0.78867513459481287f;
}

__device__ double d_acc;           // zero-init; reset by last block each launch
__device__ unsigned int d_count;   // zero-init; reset by last block each launch

__device__ __forceinline__ float ex2f(float x) {
    float y;
    asm("ex2.approx.ftz.f32 %0, %1;" : "=f"(y) : "f"(x));
    return y;
}
__device__ __forceinline__ float rcpf(float x) {
    float y;
    asm("rcp.approx.ftz.f32 %0, %1;" : "=f"(y) : "f"(x));
    return y;
}

// erfinv(1-2p) = Phi^{-1}(1-p)/sqrt(2), valid p in (0.05, 0.95).
// Cubic in L = log2(4p(1-p)); fit on L in [-2.4, 0], abs err <= ~4e-5.
__device__ __forceinline__ float ninv_half(float p) {
    const float x = fmaf(-2.0f, p, 1.0f);      // 1-2p
    const float t = fmaf(-x, x, 1.0f);         // 4p(1-p) in [0.19, 1]
    const float L = __log2f(t);
    float P = fmaf(7.9373e-4f, L, 5.51608e-3f);
    P = fmaf(P, L, -0.160841f);
    P = fmaf(P, L, 0.886227f);
    return x * P;
}

// A&S 7.1.25 erfc 3-term with the 0.5 prefactor folded into coefficients;
// t precomputed, eneg = exp(-h^2/2). Returns Phi(h).
__device__ __forceinline__ float phi_poly(float h, float t, float eneg) {
    float poly = fmaf(0.3739278f, t, -0.0479399f);
    poly = fmaf(poly, t, 0.1740121f);
    const float half_erfc = poly * t * eneg;
    return (h >= 0.0f) ? (1.0f - half_erfc) : half_erfc;
}

__global__ __launch_bounds__(TPB, 5) void loss_kernel(
    const float* __restrict__ yhat, const float* __restrict__ yv,
    const float* __restrict__ g12, const float* __restrict__ g34,
    const float* __restrict__ g3412, const float* __restrict__ s1p,
    const float* __restrict__ s2p, int n, float* __restrict__ out) {
    __shared__ float s_sc[11];
    __shared__ float4 s_cw[NQ];      // (c0, lw, A=c0*hx, pad)
    __shared__ double sw[TPB / 32];  // per-warp partials

    const int tid = threadIdx.x;
    const int half = n >> 1;
    const int gid = blockIdx.x * blockDim.x + tid;
    const int stride = gridDim.x * blockDim.x;

    const float2* p3p = (const float2*)yhat;
    const float2* m1p = (const float2*)(yhat + n);
    const float2* p4p = (const float2*)(yhat + 2 * n);
    const float2* m2p = (const float2*)(yhat + 3 * n);
    const float2* l3p = (const float2*)yv;
    const float2* r1p = (const float2*)(yv + n);
    const float2* l4p = (const float2*)(yv + 2 * n);
    const float2* r2p = (const float2*)(yv + 3 * n);

    // ---- prologue loads FIRST: overlap DRAM latency with setup + barriers ----
    float2 p3, p4, m1, m2, r1, r2;
    int i = gid;
    if (i < half) {
        p3 = __ldg(p3p + i); p4 = __ldg(p4p + i);
        m1 = __ldg(m1p + i); m2 = __ldg(m2p + i);
        r1 = __ldg(r1p + i); r2 = __ldg(r2p + i);
    }

    if (tid == 0) {
        const float a = g12[0], b = g12[1], c = g12[2], d = g12[3];
        const float inv_det = 1.0f / (a * d - b * c);
        const float i00 = d * inv_det, i01 = -b * inv_det;
        const float i10 = -c * inv_det, i11 = a * inv_det;
        const float t0 = g3412[0], t1 = g3412[1], t2 = g3412[2], t3 = g3412[3];
        const float M00 = t0 * i00 + t1 * i10, M01 = t0 * i01 + t1 * i11;
        const float M10 = t2 * i00 + t3 * i10, M11 = t2 * i01 + t3 * i11;
        const float gs00 = g34[0] - (M00 * t0 + M01 * t1);
        const float gs01 = g34[1] - (M00 * t2 + M01 * t3);
        const float gs11 = g34[3] - (M10 * t2 + M11 * t3);
        const float s1g = sqrtf(gs00), s2g = sqrtf(gs11);
        const float rho = gs01 / (s1g * s2g);
        const float is1 = 1.0f / s1p[0], is2 = 1.0f / s2p[0];
        const float iv1 = 1.0f / s1g, iv2 = 1.0f / s2g;
        s_sc[0] = M00 * is1 * iv1; s_sc[1] = M01 * is2 * iv1;
        s_sc[2] = M10 * is1 * iv2; s_sc[3] = M11 * is2 * iv2;
        s_sc[4] = i00 * is1 * is1; s_sc[5] = (i01 + i10) * is1 * is2;
        s_sc[6] = i11 * is2 * is2;
        s_sc[7] = 1.41421356237309505f * iv1;   // sqrt(2)/s1g
        s_sc[8] = 1.41421356237309505f * iv2;   // sqrt(2)/s2g
        s_sc[9] = (rho >= 0.0f) ? 1.0f : -1.0f;
        s_sc[10] = 2.0f * rho;
    }
    __syncthreads();
    if (tid < NQ) {
        const float rho = 0.5f * s_sc[10];
        const float hx = hx_of(tid);
        const float r = rho * hx;
        const float omr2 = 1.0f - r * r;
        float4 cw;
        cw.x = 1.4426950408889634f / (2.0f * omr2);                    // c0
        const float amp = fabsf(rho) * 0.5f / (6.283185307179586f * sqrtf(omr2));
        cw.y = __log2f(amp);                                           // lw
        cw.z = cw.x * hx;                                              // A
        cw.w = 0.0f;
        s_cw[tid] = cw;
    }
    __syncthreads();

    const float M00 = s_sc[0], M01 = s_sc[1], M10 = s_sc[2], M11 = s_sc[3];
    const float i00 = s_sc[4], i01s = s_sc[5], i11 = s_sc[6];
    const float rt2s1 = s_sc[7], rt2s2 = s_sc[8], sgn = s_sc[9], rho2 = s_sc[10];
    const float4 cw0 = s_cw[0];
    const float4 cw1 = s_cw[1];

    float tsum = 0.0f;

    while (i < half) {
        // in-body label loads (used only at the final Ci select)
        const float2 l3 = __ldg(l3p + i);
        const float2 l4 = __ldg(l4p + i);

        // ---- preamble: consume loaded registers ----
        const float d1a = r1.x - m1.x, d2a = r2.x - m2.x;
        const float mu1a = fmaf(M00, d1a, M01 * d2a);   // mu1/s1g
        const float mu2a = fmaf(M10, d1a, M11 * d2a);   // mu2/s2g
        const float quada = fmaf(d1a, fmaf(i00, d1a, i01s * d2a), i11 * d2a * d2a);
        const float ha = fmaf(ninv_half(p3.x), rt2s1, -mu1a);
        const float ka = fmaf(ninv_half(p4.x), rt2s2, -mu2a);

        const float d1b = r1.y - m1.y, d2b = r2.y - m2.y;
        const float mu1b = fmaf(M00, d1b, M01 * d2b);
        const float mu2b = fmaf(M10, d1b, M11 * d2b);
        const float quadb = fmaf(d1b, fmaf(i00, d1b, i01s * d2b), i11 * d2b * d2b);
        const float hb = fmaf(ninv_half(p3.y), rt2s1, -mu1b);
        const float kb = fmaf(ninv_half(p4.y), rt2s2, -mu2b);

        // ---- prefetch next iteration into the now-dead load registers ----
        const int inext = i + stride;
        const int ipf = (inext < half) ? inext : i;
        p3 = __ldg(p3p + ipf); p4 = __ldg(p4p + ipf);
        m1 = __ldg(m1p + ipf); m2 = __ldg(m2p + ipf);
        r1 = __ldg(r1p + ipf); r2 = __ldg(r2p + ipf);

        // ---- main math overlaps the prefetch latency ----
        const float h2a = ha * ha, k2a = ka * ka;
        const float eha = ex2f(-0.72134752044448170f * h2a);
        const float eka = ex2f(-0.72134752044448170f * k2a);
        const float h2b = hb * hb, k2b = kb * kb;
        const float ehb = ex2f(-0.72134752044448170f * h2b);
        const float ekb = ex2f(-0.72134752044448170f * k2b);

        // paired phi t-computation: one rcp per element (t = 1/(1+0.47047*z))
        const float uha = fmaf(0.33271137123566316f, fabsf(ha), 1.0f);
        const float uka = fmaf(0.33271137123566316f, fabsf(ka), 1.0f);
        const float invta = rcpf(uha * uka);
        const float P3a = phi_poly(ha, uka * invta, eha);
        const float P4a = phi_poly(ka, uha * invta, eka);

        const float uhb = fmaf(0.33271137123566316f, fabsf(hb), 1.0f);
        const float ukb = fmaf(0.33271137123566316f, fabsf(kb), 1.0f);
        const float invtb = rcpf(uhb * ukb);
        const float P3b = phi_poly(hb, ukb * invtb, ehb);
        const float P4b = phi_poly(kb, uhb * invtb, ekb);

        const float mSa = -(h2a + k2a);
        const float HKa = rho2 * ha * ka;
        const float mSb = -(h2b + k2b);
        const float HKb = rho2 * hb * kb;

        // GL-2 quadrature: expo = HK*A_q + (c0_q*mS + lw_q)
        const float acca = ex2f(fmaf(HKa, cw0.z, fmaf(cw0.x, mSa, cw0.y)))
                         + ex2f(fmaf(HKa, cw1.z, fmaf(cw1.x, mSa, cw1.y)));
        const float accb = ex2f(fmaf(HKb, cw0.z, fmaf(cw0.x, mSb, cw0.y)))
                         + ex2f(fmaf(HKb, cw1.z, fmaf(cw1.x, mSb, cw1.y)));

        const float Ba = fmaf(P3a, P4a, sgn * acca);
        const float Bb = fmaf(P3b, P4b, sgn * accb);

        const bool b3a = !(l3.x < 1.0f), b4a = !(l4.x < 1.0f);
        const bool b3b = !(l3.y < 1.0f), b4b = !(l4.y < 1.0f);
        const float Cia = b3a ? (b4a ? (1.0f - P3a - P4a + Ba) : (P4a - Ba))
                              : (b4a ? (P3a - Ba) : Ba);
        const float Cib = b3b ? (b4b ? (1.0f - P3b - P4b + Bb) : (P4b - Bb))
                              : (b4b ? (P3b - Bb) : Bb);

        // paired log: one lg2 per two elements
        const float prod = fmaxf(Cia, 1e-30f) * fmaxf(Cib, 1e-30f);
        tsum += fmaf(-0.5f, quada + quadb, __logf(prod));

        i = inext;
    }

    // odd-n tail: one scalar element handled by global thread 0
    if ((n & 1) && gid == 0) {
        const int j = n - 1;
        const float d1 = yv[n + j] - yhat[n + j];
        const float d2 = yv[3 * n + j] - yhat[3 * n + j];
        const float mu1 = fmaf(M00, d1, M01 * d2);
        const float mu2 = fmaf(M10, d1, M11 * d2);
        const float quad = fmaf(d1, fmaf(i00, d1, i01s * d2), i11 * d2 * d2);
        const float h = fmaf(ninv_half(yhat[j]), rt2s1, -mu1);
        const float k = fmaf(ninv_half(yhat[2 * n + j]), rt2s2, -mu2);
        const float h2 = h * h, k2 = k * k;
        const float eh = ex2f(-0.72134752044448170f * h2);
        const float ek = ex2f(-0.72134752044448170f * k2);
        const float uh = fmaf(0.33271137123566316f, fabsf(h), 1.0f);
        const float uk = fmaf(0.33271137123566316f, fabsf(k), 1.0f);
        const float invt = rcpf(uh * uk);
        const float P3 = phi_poly(h, uk * invt, eh);
        const float P4 = phi_poly(k, uh * invt, ek);
        const float mS = -(h2 + k2);
        const float HK = rho2 * h * k;
        const float acc = ex2f(fmaf(HK, cw0.z, fmaf(cw0.x, mS, cw0.y)))
                        + ex2f(fmaf(HK, cw1.z, fmaf(cw1.x, mS, cw1.y)));
        const float B = fmaf(P3, P4, sgn * acc);
        const bool b3 = !(yv[j] < 1.0f), b4 = !(yv[2 * n + j] < 1.0f);
        const float Ci = b3 ? (b4 ? (1.0f - P3 - P4 + B) : (P4 - B))
                            : (b4 ? (P3 - B) : B);
        tsum += fmaf(-0.5f, quad, __logf(fmaxf(Ci, 1e-30f)));
    }

    // ---- deterministic reduction: warp shuffle (fixed lane order) ----
    double v = (double)tsum;
#pragma unroll
    for (int off = 16; off > 0; off >>= 1) {
        v += __shfl_down_sync(0xFFFFFFFFu, v, off);
    }
    const int wid = tid >> 5;
    if ((tid & 31) == 0) sw[wid] = v;
    __syncthreads();
    if (wid == 0) {
        double w = (tid < TPB / 32) ? sw[tid] : 0.0;
#pragma unroll
        for (int off = 4; off > 0; off >>= 1) {
            w += __shfl_down_sync(0xFFFFFFFFu, w, off);
        }
        // grid reduction: one double atomicAdd per block; ticket-elected
        // last block publishes the result and resets state for graph replay.
        if (tid == 0) {
            atomicAdd(&d_acc, w);
            __threadfence();
            const unsigned int old = atomicAdd(&d_count, 1u);
            if (old == gridDim.x - 1) {
                __threadfence();
                const double total = atomicAdd(&d_acc, 0.0);
                out[0] = (float)(-total);
                d_acc = 0.0;
                d_count = 0;
            }
        }
    }
}

extern "C" void kernel_launch(void* const* d_in, const int* in_sizes, int n_in,
                              void* d_out, int out_size) {
    const float* yhat = (const float*)d_in[0];
    const float* yv = (const float*)d_in[1];
    const float* g12 = (const float*)d_in[2];
    const float* g34 = (const float*)d_in[3];
    const float* g3412 = (const float*)d_in[4];
    const float* s1 = (const float*)d_in[5];
    const float* s2 = (const float*)d_in[6];
    const int n = in_sizes[0] / 4;

    loss_kernel<<<NBLOCKS, TPB>>>(yhat, yv, g12, g34, g3412, s1, s2, n, (float*)d_out);
}